// round 1
// baseline (speedup 1.0000x reference)
#include <cuda_runtime.h>
#include <math.h>

#define B   32
#define L   2048
#define DC  512
#define DQ  1024
#define H   256
#define NW  7
#define HS  4           // H slices in kernel2
#define JS  (H / HS)    // 64 hidden units per slice

// scratch (no allocations allowed)
__device__ float g_params[B][4];        // alpha, beta, kappa, center
__device__ float g_spart[B][NW][HS];    // partial scores per H-slice

// ---------------------------------------------------------------------------
// Kernel 1: h = tanh(q@Wq + bq); stat = h@Ws + bs; alpha/beta/kappa/center
// grid: B blocks, 256 threads
// ---------------------------------------------------------------------------
__global__ void k1_stat(const float* __restrict__ query,
                        const float* __restrict__ kappa_prev,
                        const float* __restrict__ Wq,
                        const float* __restrict__ bq,
                        const float* __restrict__ Ws,
                        const float* __restrict__ bs)
{
    int b = blockIdx.x;
    int t = threadIdx.x;                 // 256 threads

    __shared__ float sq[DQ];
    __shared__ float sred[4][H];
    __shared__ float sh[H];
    __shared__ float swr[8];
    __shared__ float sstat[3];

    // stage query row
    {
        const float4* q4 = (const float4*)(query + (size_t)b * DQ);
        for (int i = t; i < DQ / 4; i += 256)
            ((float4*)sq)[i] = q4[i];
    }
    __syncthreads();

    // thread tiling: 4 i-groups x 64 j-threads, each j-thread owns 4 j's
    int ig = t >> 6;          // 0..3
    int jt = t & 63;          // 0..63
    int j0 = jt * 4;

    float a0 = 0.f, a1 = 0.f, a2 = 0.f, a3 = 0.f;
    int ibase = ig * 256;
    for (int ii = 0; ii < 256; ii += 4) {
        float4 qv = *((const float4*)(sq + ibase + ii));
        float qs[4] = {qv.x, qv.y, qv.z, qv.w};
#pragma unroll
        for (int u = 0; u < 4; u++) {
            float4 wv = *((const float4*)(Wq + (size_t)(ibase + ii + u) * H + j0));
            a0 += qs[u] * wv.x;
            a1 += qs[u] * wv.y;
            a2 += qs[u] * wv.z;
            a3 += qs[u] * wv.w;
        }
    }
    sred[ig][j0 + 0] = a0;
    sred[ig][j0 + 1] = a1;
    sred[ig][j0 + 2] = a2;
    sred[ig][j0 + 3] = a3;
    __syncthreads();

    // h[j], one j per thread (H == 256 == blockDim)
    {
        float s = bq[t];
#pragma unroll
        for (int g = 0; g < 4; g++) s += sred[g][t];
        sh[t] = tanhf(s);
    }
    __syncthreads();

    // stat[k] = sum_j h[j]*Ws[j][k] + bs[k]
    for (int k = 0; k < 3; k++) {
        float v = sh[t] * Ws[t * 3 + k];
#pragma unroll
        for (int o = 16; o; o >>= 1)
            v += __shfl_down_sync(0xffffffffu, v, o);
        if ((t & 31) == 0) swr[t >> 5] = v;
        __syncthreads();
        if (t == 0) {
            float s = bs[k];
#pragma unroll
            for (int w = 0; w < 8; w++) s += swr[w];
            sstat[k] = s;
        }
        __syncthreads();
    }

    if (t == 0) {
        float alpha = expf(sstat[0]);
        float beta  = expf(sstat[1]);
        float kappa = expf(sstat[2]) + kappa_prev[b];
        g_params[b][0] = alpha;
        g_params[b][1] = beta;
        g_params[b][2] = kappa;
        g_params[b][3] = rintf(kappa);   // jnp.round = round-half-even = rintf
    }
}

// ---------------------------------------------------------------------------
// Kernel 2: MLP scorer at the 7 window positions only.
// hidden[w][j] = tanh( sum_i ctx[b,l_w,i]*W1[i,j] + sum_i q[i]*W1[512+i,j] + b1[j] )
// partial_score[b][w][slice] = sum_{j in slice} hidden[w][j] * W2[j]
// grid: (HS, B) blocks, 256 threads. W1 read once per (batch, slice).
// ---------------------------------------------------------------------------
__global__ void k2_score(const float* __restrict__ ctx,
                         const float* __restrict__ query,
                         const float* __restrict__ W1,
                         const float* __restrict__ b1,
                         const float* __restrict__ W2)
{
    int s = blockIdx.x;      // H slice 0..3
    int b = blockIdx.y;
    int t = threadIdx.x;     // 256 threads

    __shared__ float sq[DQ];              // 4 KB
    __shared__ float sctx[NW * DC];       // 14 KB
    __shared__ float sred[16 * JS];       // 4 KB
    __shared__ float sqtot[JS];
    __shared__ float swr2[2];
    __shared__ float s_center;

    if (t == 0) s_center = g_params[b][3];

    // stage query
    {
        const float4* q4 = (const float4*)(query + (size_t)b * DQ);
        for (int i = t; i < DQ / 4; i += 256)
            ((float4*)sq)[i] = q4[i];
    }
    __syncthreads();
    int center = (int)s_center;

    // stage the 7 ctx rows (zero-filled out of range)
    for (int c = t; c < NW * (DC / 4); c += 256) {
        int w  = c / (DC / 4);
        int i4 = c % (DC / 4);
        int l  = center - 3 + w;
        float4 v = make_float4(0.f, 0.f, 0.f, 0.f);
        if (l >= 0 && l < L)
            v = ((const float4*)(ctx + ((size_t)b * L + l) * DC))[i4];
        ((float4*)sctx)[w * (DC / 4) + i4] = v;
    }
    __syncthreads();

    // thread tiling: 16 i-groups x 16 j-threads, 4 j per thread
    int ig = t >> 4;          // 0..15
    int jt = t & 15;          // 0..15
    int j0 = s * JS + jt * 4;

    // ---- query part of W1 (w-invariant, hoisted) ----
    float aq[4] = {0.f, 0.f, 0.f, 0.f};
    int qi0 = ig * 64;
    for (int ii = 0; ii < 64; ii += 4) {
        float4 qv = *((const float4*)(sq + qi0 + ii));
        float qs[4] = {qv.x, qv.y, qv.z, qv.w};
#pragma unroll
        for (int u = 0; u < 4; u++) {
            float4 wv = *((const float4*)(W1 + (size_t)(DC + qi0 + ii + u) * H + j0));
            aq[0] += qs[u] * wv.x;
            aq[1] += qs[u] * wv.y;
            aq[2] += qs[u] * wv.z;
            aq[3] += qs[u] * wv.w;
        }
    }

    // ---- ctx part: 7 window accumulators in registers, W1 read once ----
    float ac[NW][4];
#pragma unroll
    for (int w = 0; w < NW; w++)
#pragma unroll
        for (int k = 0; k < 4; k++) ac[w][k] = 0.f;

    int ci0 = ig * 32;
    for (int ii = 0; ii < 32; ii += 4) {
        float4 wv[4];
#pragma unroll
        for (int u = 0; u < 4; u++)
            wv[u] = *((const float4*)(W1 + (size_t)(ci0 + ii + u) * H + j0));
#pragma unroll
        for (int w = 0; w < NW; w++) {
            float4 cv = *((const float4*)(sctx + w * DC + ci0 + ii));
            float cs[4] = {cv.x, cv.y, cv.z, cv.w};
#pragma unroll
            for (int u = 0; u < 4; u++) {
                ac[w][0] += cs[u] * wv[u].x;
                ac[w][1] += cs[u] * wv[u].y;
                ac[w][2] += cs[u] * wv[u].z;
                ac[w][3] += cs[u] * wv[u].w;
            }
        }
    }

    // ---- reduce qpart over 16 i-groups ----
#pragma unroll
    for (int k = 0; k < 4; k++)
        sred[ig * JS + jt * 4 + k] = aq[k];
    __syncthreads();
    if (t < JS) {
        float sum = 0.f;
#pragma unroll
        for (int g = 0; g < 16; g++) sum += sred[g * JS + t];
        sqtot[t] = sum;
    }
    __syncthreads();

    // ---- per window: reduce, tanh, dot with W2, block-sum ----
    for (int w = 0; w < NW; w++) {
#pragma unroll
        for (int k = 0; k < 4; k++)
            sred[ig * JS + jt * 4 + k] = ac[w][k];
        __syncthreads();

        float contrib = 0.f;
        if (t < JS) {
            int j = s * JS + t;
            float hsum = sqtot[t] + b1[j];
#pragma unroll
            for (int g = 0; g < 16; g++) hsum += sred[g * JS + t];
            contrib = tanhf(hsum) * W2[j];
        }
#pragma unroll
        for (int o = 16; o; o >>= 1)
            contrib += __shfl_down_sync(0xffffffffu, contrib, o);
        if (t == 0 || t == 32) swr2[t >> 5] = contrib;
        __syncthreads();
        if (t == 0) g_spart[b][w][s] = swr2[0] + swr2[1];
        __syncthreads();   // sred reused next iteration
    }
}

// ---------------------------------------------------------------------------
// Kernel 3: posterior over the 7-window, normalize, expected_ctx, p_ctx
// grid: B blocks, 256 threads
// ---------------------------------------------------------------------------
__global__ void k3_final(const float* __restrict__ ctx,
                         const float* __restrict__ b2,
                         float* __restrict__ out,
                         int out_size)
{
    int b = blockIdx.x;
    int t = threadIdx.x;   // 256

    float alpha  = g_params[b][0];
    float beta   = g_params[b][1];
    float kappa  = g_params[b][2];
    int   center = (int)g_params[b][3];
    float b2v    = b2[0];

    float pw[NW];
    float psum = 0.f;
#pragma unroll
    for (int w = 0; w < NW; w++) {
        int l = center - 3 + w;
        float p = 0.f;
        if (l >= 0 && l < L) {
            float sc = b2v;
#pragma unroll
            for (int s2 = 0; s2 < HS; s2++) sc += g_spart[b][w][s2];
            float d = (float)l - kappa;
            p = alpha * expf(sc - beta * d * d);
        }
        pw[w] = p;
        psum += p;
    }
    float inv = 1.f / psum;
#pragma unroll
    for (int w = 0; w < NW; w++) pw[w] *= inv;

    bool both   = (out_size >= B * (DC + L));
    bool only_p = (out_size == B * L);

    if (!only_p) {
        // expected_ctx[b][d] = sum_w p[w] * ctx[b][l_w][d]
        for (int d = t; d < DC; d += 256) {
            float acc = 0.f;
#pragma unroll
            for (int w = 0; w < NW; w++) {
                int l = center - 3 + w;
                if (l >= 0 && l < L)
                    acc += pw[w] * ctx[((size_t)b * L + l) * DC + d];
            }
            out[(size_t)b * DC + d] = acc;
        }
    }
    if (both || only_p) {
        float* op = only_p ? out : (out + (size_t)B * DC);
        for (int pos = t; pos < L; pos += 256) {
            int r = pos - (center - 3);
            float v = (r >= 0 && r < NW) ? pw[r] : 0.f;
            op[(size_t)b * L + pos] = v;
        }
    }
}

// ---------------------------------------------------------------------------
extern "C" void kernel_launch(void* const* d_in, const int* in_sizes, int n_in,
                              void* d_out, int out_size)
{
    const float* query = (const float*)d_in[0];
    const float* ctx   = (const float*)d_in[1];
    const float* kprev = (const float*)d_in[2];
    const float* Wq    = (const float*)d_in[3];
    const float* bq    = (const float*)d_in[4];
    const float* Ws    = (const float*)d_in[5];
    const float* bs    = (const float*)d_in[6];
    const float* W1    = (const float*)d_in[7];
    const float* b1    = (const float*)d_in[8];
    const float* W2    = (const float*)d_in[9];
    const float* b2    = (const float*)d_in[10];

    k1_stat <<<B, 256>>>(query, kprev, Wq, bq, Ws, bs);
    k2_score<<<dim3(HS, B), 256>>>(ctx, query, W1, b1, W2);
    k3_final<<<B, 256>>>(ctx, b2, (float*)d_out, out_size);
}

// round 2
// speedup vs baseline: 1.1383x; 1.1383x over previous
#include <cuda_runtime.h>
#include <math.h>

#define B   32
#define L   2048
#define DC  512
#define DQ  1024
#define H   256
#define NW  7
#define HS  4           // H slices in kernel2
#define JS  (H / HS)    // 64 hidden units per slice
#define IG1 8           // i-chunks in k1a (1024/128)
#define IC1 128         // i-chunk size in k1a
#define JC1 4           // j-chunks in k1a (256/64)
#define JT1 64          // j-chunk size in k1a

// scratch (no allocations allowed)
__device__ float g_pre[2][IG1][B][H];   // partial pre-activations: [0]=h-pre, [1]=q-part of MLP
__device__ float g_qtot[B][H];          // reduced query-part of MLP hidden pre-activation
__device__ float g_params[B][4];        // alpha, beta, kappa, center
__device__ float g_spart[B][NW][HS];    // partial scores per H-slice

// ---------------------------------------------------------------------------
// Kernel 1a: batched weight-shared partial GEMM.
//   m=0: pre_h  += q[b, i-chunk] @ Wq[i-chunk, j-chunk]
//   m=1: pre_q  += q[b, i-chunk] @ W1[512+i-chunk, j-chunk]
// grid: (IG1, JC1, 2) = 64 blocks, 256 threads. Each weight tile read ONCE.
// ---------------------------------------------------------------------------
__global__ void k1a_pre(const float* __restrict__ query,
                        const float* __restrict__ Wq,
                        const float* __restrict__ W1)
{
    int ig = blockIdx.x;     // 0..7
    int jc = blockIdx.y;     // 0..3
    int m  = blockIdx.z;     // 0..1
    int t  = threadIdx.x;    // 256

    const float* W = (m == 0) ? Wq : (W1 + (size_t)DC * H);
    int i0 = ig * IC1;
    int j0 = jc * JT1;

    __shared__ float sW[IC1 * JT1];   // 32 KB
    __shared__ float sq[B * IC1];     // 16 KB

    // stage weight tile: 128 rows x 64 cols
    for (int idx = t; idx < IC1 * (JT1 / 4); idx += 256) {
        int r  = idx >> 4;           // row 0..127
        int c4 = idx & 15;           // col-quad 0..15
        ((float4*)sW)[r * (JT1 / 4) + c4] =
            *((const float4*)(W + (size_t)(i0 + r) * H + j0 + c4 * 4));
    }
    // stage query chunk for all batches: 32 rows x 128
    for (int idx = t; idx < B * (IC1 / 4); idx += 256) {
        int b  = idx >> 5;           // 0..31
        int c4 = idx & 31;           // 0..31
        ((float4*)sq)[b * (IC1 / 4) + c4] =
            *((const float4*)(query + (size_t)b * DQ + i0 + c4 * 4));
    }
    __syncthreads();

    // thread map: jt = t&15 owns 4 j's, bg = t>>4 owns 2 batches
    int jt = t & 15;
    int bg = t >> 4;
    int ja = jt * 4;
    int b0 = bg * 2;

    float a0[4] = {0.f, 0.f, 0.f, 0.f};
    float a1[4] = {0.f, 0.f, 0.f, 0.f};
#pragma unroll 8
    for (int i = 0; i < IC1; i++) {
        float4 w = *((const float4*)(sW + i * JT1 + ja));
        float qa = sq[(b0 + 0) * IC1 + i];
        float qb = sq[(b0 + 1) * IC1 + i];
        a0[0] += qa * w.x; a0[1] += qa * w.y; a0[2] += qa * w.z; a0[3] += qa * w.w;
        a1[0] += qb * w.x; a1[1] += qb * w.y; a1[2] += qb * w.z; a1[3] += qb * w.w;
    }
    *((float4*)&g_pre[m][ig][b0 + 0][j0 + ja]) = *((float4*)a0);
    *((float4*)&g_pre[m][ig][b0 + 1][j0 + ja]) = *((float4*)a1);
}

// ---------------------------------------------------------------------------
// Kernel 1b: reduce partials -> h (tanh), qtot; stat = h@Ws + bs; params.
// grid: B blocks, 256 threads (one j per thread)
// ---------------------------------------------------------------------------
__global__ void k1b_stat(const float* __restrict__ kappa_prev,
                         const float* __restrict__ bq,
                         const float* __restrict__ Ws,
                         const float* __restrict__ bs)
{
    int b = blockIdx.x;
    int t = threadIdx.x;    // j = t

    __shared__ float sh[H];
    __shared__ float swr[8];
    __shared__ float sstat[3];

    float s = bq[t];
    float qt = 0.f;
#pragma unroll
    for (int ig = 0; ig < IG1; ig++) {
        s  += g_pre[0][ig][b][t];
        qt += g_pre[1][ig][b][t];
    }
    g_qtot[b][t] = qt;
    sh[t] = tanhf(s);
    __syncthreads();

    for (int k = 0; k < 3; k++) {
        float v = sh[t] * Ws[t * 3 + k];
#pragma unroll
        for (int o = 16; o; o >>= 1)
            v += __shfl_down_sync(0xffffffffu, v, o);
        if ((t & 31) == 0) swr[t >> 5] = v;
        __syncthreads();
        if (t == 0) {
            float acc = bs[k];
#pragma unroll
            for (int w = 0; w < 8; w++) acc += swr[w];
            sstat[k] = acc;
        }
        __syncthreads();
    }

    if (t == 0) {
        float alpha = expf(sstat[0]);
        float beta  = expf(sstat[1]);
        float kappa = expf(sstat[2]) + kappa_prev[b];
        g_params[b][0] = alpha;
        g_params[b][1] = beta;
        g_params[b][2] = kappa;
        g_params[b][3] = rintf(kappa);   // jnp.round = round-half-even
    }
}

// ---------------------------------------------------------------------------
// Kernel 2: ctx part of MLP at the 7 window positions (query part precomputed).
// hidden[w][j] = tanh( sum_i ctx[b,l_w,i]*W1[i,j] + qtot[b][j] + b1[j] )
// partial_score[b][w][slice] = sum_{j in slice} hidden[w][j] * W2[j]
// grid: (HS, B) blocks, 256 threads.
// ---------------------------------------------------------------------------
__global__ void k2_score(const float* __restrict__ ctx,
                         const float* __restrict__ W1,
                         const float* __restrict__ b1,
                         const float* __restrict__ W2)
{
    int s = blockIdx.x;      // H slice 0..3
    int b = blockIdx.y;
    int t = threadIdx.x;     // 256 threads

    __shared__ float sctx[NW * DC];       // 14 KB
    __shared__ float sred[16 * JS];       // 4 KB
    __shared__ float swr2[2];

    int center = (int)g_params[b][3];

    // stage the 7 ctx rows (zero-filled out of range)
    for (int c = t; c < NW * (DC / 4); c += 256) {
        int w  = c / (DC / 4);
        int i4 = c % (DC / 4);
        int l  = center - 3 + w;
        float4 v = make_float4(0.f, 0.f, 0.f, 0.f);
        if (l >= 0 && l < L)
            v = ((const float4*)(ctx + ((size_t)b * L + l) * DC))[i4];
        ((float4*)sctx)[w * (DC / 4) + i4] = v;
    }
    __syncthreads();

    // thread tiling: 16 i-groups x 16 j-threads, 4 j per thread
    int ig = t >> 4;          // 0..15
    int jt = t & 15;          // 0..15
    int j0 = s * JS + jt * 4;

    float ac[NW][4];
#pragma unroll
    for (int w = 0; w < NW; w++)
#pragma unroll
        for (int k = 0; k < 4; k++) ac[w][k] = 0.f;

    int ci0 = ig * 32;
    for (int ii = 0; ii < 32; ii += 4) {
        float4 wv[4];
#pragma unroll
        for (int u = 0; u < 4; u++)
            wv[u] = *((const float4*)(W1 + (size_t)(ci0 + ii + u) * H + j0));
#pragma unroll
        for (int w = 0; w < NW; w++) {
            float4 cv = *((const float4*)(sctx + w * DC + ci0 + ii));
            float cs[4] = {cv.x, cv.y, cv.z, cv.w};
#pragma unroll
            for (int u = 0; u < 4; u++) {
                ac[w][0] += cs[u] * wv[u].x;
                ac[w][1] += cs[u] * wv[u].y;
                ac[w][2] += cs[u] * wv[u].z;
                ac[w][3] += cs[u] * wv[u].w;
            }
        }
    }

    // per window: reduce over 16 i-groups, add qtot+b1, tanh, dot W2, block-sum
    for (int w = 0; w < NW; w++) {
#pragma unroll
        for (int k = 0; k < 4; k++)
            sred[ig * JS + jt * 4 + k] = ac[w][k];
        __syncthreads();

        float contrib = 0.f;
        if (t < JS) {
            int j = s * JS + t;
            float hsum = g_qtot[b][j] + b1[j];
#pragma unroll
            for (int g = 0; g < 16; g++) hsum += sred[g * JS + t];
            contrib = tanhf(hsum) * W2[j];
        }
#pragma unroll
        for (int o = 16; o; o >>= 1)
            contrib += __shfl_down_sync(0xffffffffu, contrib, o);
        if (t == 0 || t == 32) swr2[t >> 5] = contrib;
        __syncthreads();
        if (t == 0) g_spart[b][w][s] = swr2[0] + swr2[1];
        __syncthreads();   // sred reused next iteration
    }
}

// ---------------------------------------------------------------------------
// Kernel 3: posterior over the 7-window, normalize, expected_ctx, p_ctx
// grid: B blocks, 256 threads
// ---------------------------------------------------------------------------
__global__ void k3_final(const float* __restrict__ ctx,
                         const float* __restrict__ b2,
                         float* __restrict__ out,
                         int out_size)
{
    int b = blockIdx.x;
    int t = threadIdx.x;   // 256

    float alpha  = g_params[b][0];
    float beta   = g_params[b][1];
    float kappa  = g_params[b][2];
    int   center = (int)g_params[b][3];
    float b2v    = b2[0];

    float pw[NW];
    float psum = 0.f;
#pragma unroll
    for (int w = 0; w < NW; w++) {
        int l = center - 3 + w;
        float p = 0.f;
        if (l >= 0 && l < L) {
            float sc = b2v;
#pragma unroll
            for (int s2 = 0; s2 < HS; s2++) sc += g_spart[b][w][s2];
            float d = (float)l - kappa;
            p = alpha * expf(sc - beta * d * d);
        }
        pw[w] = p;
        psum += p;
    }
    float inv = 1.f / psum;
#pragma unroll
    for (int w = 0; w < NW; w++) pw[w] *= inv;

    bool both   = (out_size >= B * (DC + L));
    bool only_p = (out_size == B * L);

    if (!only_p) {
        for (int d = t; d < DC; d += 256) {
            float acc = 0.f;
#pragma unroll
            for (int w = 0; w < NW; w++) {
                int l = center - 3 + w;
                if (l >= 0 && l < L)
                    acc += pw[w] * ctx[((size_t)b * L + l) * DC + d];
            }
            out[(size_t)b * DC + d] = acc;
        }
    }
    if (both || only_p) {
        float* op = only_p ? out : (out + (size_t)B * DC);
        for (int pos = t; pos < L; pos += 256) {
            int r = pos - (center - 3);
            float v = (r >= 0 && r < NW) ? pw[r] : 0.f;
            op[(size_t)b * L + pos] = v;
        }
    }
}

// ---------------------------------------------------------------------------
extern "C" void kernel_launch(void* const* d_in, const int* in_sizes, int n_in,
                              void* d_out, int out_size)
{
    const float* query = (const float*)d_in[0];
    const float* ctx   = (const float*)d_in[1];
    const float* kprev = (const float*)d_in[2];
    const float* Wq    = (const float*)d_in[3];
    const float* bq    = (const float*)d_in[4];
    const float* Ws    = (const float*)d_in[5];
    const float* bs    = (const float*)d_in[6];
    const float* W1    = (const float*)d_in[7];
    const float* b1    = (const float*)d_in[8];
    const float* W2    = (const float*)d_in[9];
    const float* b2    = (const float*)d_in[10];

    k1a_pre <<<dim3(IG1, JC1, 2), 256>>>(query, Wq, W1);
    k1b_stat<<<B, 256>>>(kprev, bq, Ws, bs);
    k2_score<<<dim3(HS, B), 256>>>(ctx, W1, b1, W2);
    k3_final<<<B, 256>>>(ctx, b2, (float*)d_out, out_size);
}

// round 3
// speedup vs baseline: 1.5431x; 1.3556x over previous
#include <cuda_runtime.h>
#include <math.h>

#define B   32
#define L   2048
#define DC  512
#define DQ  1024
#define H   256
#define NW  7
#define IG1 8           // i-chunks in k1a (1024/128)
#define IC1 128         // i-chunk size in k1a
#define JC1 4           // j-chunks in k1a (256/64)
#define JT1 64          // j-chunk size in k1a

// scratch (no allocations allowed)
__device__ float g_pre[2][IG1][B][H];   // [0]=h-pre partials, [1]=q-part of MLP partials

// ---------------------------------------------------------------------------
// Kernel 1a: batched weight-shared partial GEMMs + p_ctx zero-fill plane.
//   z=0: pre_h += q[b, ichunk] @ Wq[ichunk, jchunk]
//   z=1: pre_q += q[b, ichunk] @ W1[512+ichunk, jchunk]
//   z=2: zero-fill the p_ctx region of out (independent of everything)
// grid: (8, 4, 3), 256 threads
// ---------------------------------------------------------------------------
__global__ void k1a_pre(const float* __restrict__ query,
                        const float* __restrict__ Wq,
                        const float* __restrict__ W1,
                        float* __restrict__ out)
{
    int ig = blockIdx.x;     // 0..7
    int jc = blockIdx.y;     // 0..3
    int m  = blockIdx.z;     // 0..2
    int t  = threadIdx.x;    // 256

    if (m == 2) {
        // zero-fill p_ctx region: 32 blocks x 2048 floats
        int bid = ig + 8 * jc;                       // 0..31
        float4* dst = (float4*)(out + (size_t)B * DC + (size_t)bid * 2048);
        float4 z = make_float4(0.f, 0.f, 0.f, 0.f);
        dst[t]       = z;
        dst[t + 256] = z;
        return;
    }

    const float* W = (m == 0) ? Wq : (W1 + (size_t)DC * H);
    int i0 = ig * IC1;
    int j0 = jc * JT1;

    __shared__ float sW[IC1 * JT1];   // 32 KB
    __shared__ float sq[B * IC1];     // 16 KB

    for (int idx = t; idx < IC1 * (JT1 / 4); idx += 256) {
        int r  = idx >> 4;
        int c4 = idx & 15;
        ((float4*)sW)[r * (JT1 / 4) + c4] =
            *((const float4*)(W + (size_t)(i0 + r) * H + j0 + c4 * 4));
    }
    for (int idx = t; idx < B * (IC1 / 4); idx += 256) {
        int b  = idx >> 5;
        int c4 = idx & 31;
        ((float4*)sq)[b * (IC1 / 4) + c4] =
            *((const float4*)(query + (size_t)b * DQ + i0 + c4 * 4));
    }
    __syncthreads();

    int jt = t & 15;
    int bg = t >> 4;
    int ja = jt * 4;
    int b0 = bg * 2;

    float a0[4] = {0.f, 0.f, 0.f, 0.f};
    float a1[4] = {0.f, 0.f, 0.f, 0.f};
#pragma unroll 8
    for (int i = 0; i < IC1; i++) {
        float4 w = *((const float4*)(sW + i * JT1 + ja));
        float qa = sq[(b0 + 0) * IC1 + i];
        float qb = sq[(b0 + 1) * IC1 + i];
        a0[0] += qa * w.x; a0[1] += qa * w.y; a0[2] += qa * w.z; a0[3] += qa * w.w;
        a1[0] += qb * w.x; a1[1] += qb * w.y; a1[2] += qb * w.z; a1[3] += qb * w.w;
    }
    *((float4*)&g_pre[m][ig][b0 + 0][j0 + ja]) = *((float4*)a0);
    *((float4*)&g_pre[m][ig][b0 + 1][j0 + ja]) = *((float4*)a1);
}

// ---------------------------------------------------------------------------
// Kernel B: everything else for one batch per block.
//  1) reduce g_pre -> h(tanh), qtot; stat = h@Ws+bs -> alpha,beta,kappa,center
//  2) MLP ctx-part at 7 window positions over full H
//  3) posterior, normalize, expected_ctx (from smem ctx), p_ctx window values
// grid: B blocks, 1024 threads
// ---------------------------------------------------------------------------
__global__ void __launch_bounds__(1024, 1)
kB_fused(const float* __restrict__ ctx,
         const float* __restrict__ kappa_prev,
         const float* __restrict__ bq,
         const float* __restrict__ Ws,
         const float* __restrict__ bs,
         const float* __restrict__ W1,
         const float* __restrict__ b1,
         const float* __restrict__ W2,
         const float* __restrict__ b2,
         float* __restrict__ out)
{
    int b = blockIdx.x;
    int t = threadIdx.x;        // 1024
    int lane = t & 31;
    int wid  = t >> 5;          // 0..31

    __shared__ float sctx[NW * DC];     // 14 KB
    __shared__ float sred[16 * H];      // 16 KB
    __shared__ float sqt[H];            // qtot + b1
    __shared__ float swr[3][32];
    __shared__ float swr2[32];
    __shared__ float sparams[4];        // alpha, beta, kappa, center
    __shared__ float sscore[NW];
    __shared__ float spw[NW];

    // ---- 1) params + qtot ----
    float hval = 0.f;
    if (t < H) {
        float s  = bq[t];
        float qt = b1[t];
#pragma unroll
        for (int ig = 0; ig < IG1; ig++) {
            s  += g_pre[0][ig][b][t];
            qt += g_pre[1][ig][b][t];
        }
        sqt[t] = qt;
        hval = tanhf(s);
    }
    float v0 = 0.f, v1 = 0.f, v2 = 0.f;
    if (t < H) {
        v0 = hval * Ws[t * 3 + 0];
        v1 = hval * Ws[t * 3 + 1];
        v2 = hval * Ws[t * 3 + 2];
    }
#pragma unroll
    for (int o = 16; o; o >>= 1) {
        v0 += __shfl_down_sync(0xffffffffu, v0, o);
        v1 += __shfl_down_sync(0xffffffffu, v1, o);
        v2 += __shfl_down_sync(0xffffffffu, v2, o);
    }
    if (lane == 0) { swr[0][wid] = v0; swr[1][wid] = v1; swr[2][wid] = v2; }
    __syncthreads();
    if (t == 0) {
        float s0 = bs[0], s1 = bs[1], s2 = bs[2];
#pragma unroll
        for (int w = 0; w < 8; w++) { s0 += swr[0][w]; s1 += swr[1][w]; s2 += swr[2][w]; }
        float kappa = expf(s2) + kappa_prev[b];
        sparams[0] = expf(s0);
        sparams[1] = expf(s1);
        sparams[2] = kappa;
        sparams[3] = rintf(kappa);      // jnp.round = round-half-even
    }
    __syncthreads();
    int center = (int)sparams[3];

    // ---- stage 7 ctx rows (zero-filled out of range) ----
    if (t < NW * (DC / 4)) {
        int w  = t / (DC / 4);
        int i4 = t % (DC / 4);
        int l  = center - 3 + w;
        float4 v = make_float4(0.f, 0.f, 0.f, 0.f);
        if (l >= 0 && l < L)
            v = ((const float4*)(ctx + ((size_t)b * L + l) * DC))[i4];
        ((float4*)sctx)[w * (DC / 4) + i4] = v;
    }
    __syncthreads();

    // ---- 2) MLP ctx-part: 16 i-groups x 64 j-threads, 4 j per thread ----
    int igp = t >> 6;           // 0..15, 32 i-rows each
    int jt  = t & 63;           // 0..63
    int j0  = jt * 4;
    int i0  = igp * 32;

    float ac[NW][4];
#pragma unroll
    for (int w = 0; w < NW; w++)
#pragma unroll
        for (int k = 0; k < 4; k++) ac[w][k] = 0.f;

#pragma unroll 4
    for (int ii = 0; ii < 32; ii++) {
        float4 wv = *((const float4*)(W1 + (size_t)(i0 + ii) * H + j0));
#pragma unroll
        for (int w = 0; w < NW; w++) {
            float c = sctx[w * DC + i0 + ii];
            ac[w][0] += c * wv.x;
            ac[w][1] += c * wv.y;
            ac[w][2] += c * wv.z;
            ac[w][3] += c * wv.w;
        }
    }

    // ---- per-window: reduce over i-groups, tanh, dot W2 ----
    for (int w = 0; w < NW; w++) {
#pragma unroll
        for (int k = 0; k < 4; k++)
            sred[igp * H + j0 + k] = ac[w][k];
        __syncthreads();

        float contrib = 0.f;
        if (t < H) {
            float hsum = sqt[t];
#pragma unroll
            for (int g = 0; g < 16; g++) hsum += sred[g * H + t];
            contrib = tanhf(hsum) * W2[t];
        }
#pragma unroll
        for (int o = 16; o; o >>= 1)
            contrib += __shfl_down_sync(0xffffffffu, contrib, o);
        if (lane == 0) swr2[wid] = contrib;
        __syncthreads();
        if (t == 0) {
            float s = 0.f;
#pragma unroll
            for (int g = 0; g < 8; g++) s += swr2[g];
            sscore[w] = s;
        }
        __syncthreads();
    }

    // ---- 3) posterior + normalize ----
    if (t == 0) {
        float alpha = sparams[0], beta = sparams[1], kappa = sparams[2];
        float b2v = b2[0];
        float pw[NW], psum = 0.f;
#pragma unroll
        for (int w = 0; w < NW; w++) {
            int l = center - 3 + w;
            float p = 0.f;
            if (l >= 0 && l < L) {
                float d = (float)l - kappa;
                p = alpha * expf(sscore[w] + b2v - beta * d * d);
            }
            pw[w] = p;
            psum += p;
        }
        float inv = 1.f / psum;
#pragma unroll
        for (int w = 0; w < NW; w++) spw[w] = pw[w] * inv;
    }
    __syncthreads();

    // expected_ctx from smem-staged ctx rows
    if (t < DC) {
        float acc = 0.f;
#pragma unroll
        for (int w = 0; w < NW; w++)
            acc += spw[w] * sctx[w * DC + t];
        out[(size_t)b * DC + t] = acc;
    }
    // the <=7 nonzero p_ctx entries (rest zero-filled by k1a)
    if (t >= DC && t < DC + NW) {
        int w = t - DC;
        int l = center - 3 + w;
        if (l >= 0 && l < L)
            out[(size_t)B * DC + (size_t)b * L + l] = spw[w];
    }
}

// ---------------------------------------------------------------------------
extern "C" void kernel_launch(void* const* d_in, const int* in_sizes, int n_in,
                              void* d_out, int out_size)
{
    const float* query = (const float*)d_in[0];
    const float* ctx   = (const float*)d_in[1];
    const float* kprev = (const float*)d_in[2];
    const float* Wq    = (const float*)d_in[3];
    const float* bq    = (const float*)d_in[4];
    const float* Ws    = (const float*)d_in[5];
    const float* bs    = (const float*)d_in[6];
    const float* W1    = (const float*)d_in[7];
    const float* b1    = (const float*)d_in[8];
    const float* W2    = (const float*)d_in[9];
    const float* b2    = (const float*)d_in[10];
    float* out = (float*)d_out;

    k1a_pre <<<dim3(IG1, JC1, 3), 256>>>(query, Wq, W1, out);
    kB_fused<<<B, 1024>>>(ctx, kprev, bq, Ws, bs, W1, b1, W2, b2, out);
}

// round 5
// speedup vs baseline: 1.6757x; 1.0860x over previous
#include <cuda_runtime.h>
#include <math.h>

#define B    32
#define L    2048
#define DC   512
#define DQ   1024
#define H    256
#define NW   7
#define NIC  16          // i-chunks for query GEMMs (1024/64)
#define ICR  64          // rows per i-chunk
#define NBLK 128
#define NTHR 512

// scratch (no allocations allowed)
__device__ float g_pre[2][NIC][B][H];   // [0]=h-pre partials, [1]=q-part of MLP partials
__device__ float g_spart[B][NW][4];     // per-slice partial scores
__device__ float g_params[B][4];        // alpha, beta, kappa, center
__device__ unsigned g_bar_count = 0;
__device__ unsigned g_bar_gen   = 0;    // monotonic across graph replays

__device__ __forceinline__ void grid_sync()
{
    __syncthreads();
    if (threadIdx.x == 0) {
        __threadfence();
        unsigned gen = *(volatile unsigned*)&g_bar_gen;
        if (atomicAdd(&g_bar_count, 1) == NBLK - 1) {
            g_bar_count = 0;
            __threadfence();
            *(volatile unsigned*)&g_bar_gen = gen + 1;
        } else {
            while (*(volatile unsigned*)&g_bar_gen == gen) { }
        }
        __threadfence();
    }
    __syncthreads();
}

__global__ void __launch_bounds__(NTHR, 1)
k_all(const float* __restrict__ query,
      const float* __restrict__ ctx,
      const float* __restrict__ kappa_prev,
      const float* __restrict__ Wq,
      const float* __restrict__ bq,
      const float* __restrict__ Ws,
      const float* __restrict__ bs,
      const float* __restrict__ W1,
      const float* __restrict__ b1,
      const float* __restrict__ W2,
      const float* __restrict__ b2,
      float* __restrict__ out)
{
    int bx = blockIdx.x;        // 0..127
    int t  = threadIdx.x;       // 0..511
    int lane = t & 31;
    int wid  = t >> 5;          // 0..15

    __shared__ union {
        struct { float W[ICR * 64]; float q[B * ICR]; } p1;                // 24 KB
        struct { float ctx[NW * DC]; float red[32 * 64];
                 float qt[64]; float params[4]; } p2;                      // ~22.5 KB
    } sm;
    __shared__ float swr[3][16];
    __shared__ float swr2[2];
    __shared__ float spw[NW];

    // ================= Phase 1: query GEMM partials + p_ctx zero-fill ======
    // zero-fill p_ctx region (65536 floats over 128 blocks x 512 threads)
    out[(size_t)B * DC + (size_t)bx * NTHR + t] = 0.f;

    {
        int m  = bx & 1;            // 0: Wq, 1: W1 query-half
        int jc = (bx >> 1) & 3;     // j-chunk (64 cols)
        int ic = bx >> 3;           // i-chunk (64 rows)
        const float* W = m ? (W1 + (size_t)DC * H) : Wq;
        int i0 = ic * ICR;
        int j0 = jc * 64;

        // stage weight tile 64x64 (1024 float4, 2 per thread)
        for (int idx = t; idx < ICR * 16; idx += NTHR) {
            int r  = idx >> 4;
            int c4 = idx & 15;
            *((float4*)&sm.p1.W[r * 64 + c4 * 4]) =
                *((const float4*)(W + (size_t)(i0 + r) * H + j0 + c4 * 4));
        }
        // stage query chunk for all 32 batches (512 float4, 1 per thread)
        {
            int b8 = t >> 4;
            int c4 = t & 15;
            *((float4*)&sm.p1.q[b8 * ICR + c4 * 4]) =
                *((const float4*)(query + (size_t)b8 * DQ + i0 + c4 * 4));
        }
        __syncthreads();

        int jt = t & 15;            // 4 j's each
        int bb = t >> 4;            // batch 0..31
        float a0 = 0.f, a1 = 0.f, a2 = 0.f, a3 = 0.f;
#pragma unroll 8
        for (int i = 0; i < ICR; i++) {
            float4 w = *((const float4*)&sm.p1.W[i * 64 + jt * 4]);
            float qv = sm.p1.q[bb * ICR + i];
            a0 += qv * w.x; a1 += qv * w.y; a2 += qv * w.z; a3 += qv * w.w;
        }
        float4 r4 = make_float4(a0, a1, a2, a3);
        *((float4*)&g_pre[m][ic][bb][j0 + jt * 4]) = r4;
    }

    grid_sync();

    // ================= Phase 2: params (redundant x4) + ctx-MLP slice ======
    {
        int b     = bx >> 2;
        int slice = bx & 3;

        // h-pre reduce + tanh (t<256), qtot for this slice (t<64)
        float hval = 0.f;
        if (t < H) {
            float s = bq[t];
#pragma unroll
            for (int ic = 0; ic < NIC; ic++) s += g_pre[0][ic][b][t];
            hval = tanhf(s);
        }
        if (t < 64) {
            int j = slice * 64 + t;
            float qt = b1[j];
#pragma unroll
            for (int ic = 0; ic < NIC; ic++) qt += g_pre[1][ic][b][j];
            sm.p2.qt[t] = qt;
        }
        // stat = h @ Ws + bs (all warps shuffle; t>=H contribute 0)
        float v0 = 0.f, v1 = 0.f, v2 = 0.f;
        if (t < H) {
            v0 = hval * Ws[t * 3 + 0];
            v1 = hval * Ws[t * 3 + 1];
            v2 = hval * Ws[t * 3 + 2];
        }
#pragma unroll
        for (int o = 16; o; o >>= 1) {
            v0 += __shfl_down_sync(0xffffffffu, v0, o);
            v1 += __shfl_down_sync(0xffffffffu, v1, o);
            v2 += __shfl_down_sync(0xffffffffu, v2, o);
        }
        if (lane == 0) { swr[0][wid] = v0; swr[1][wid] = v1; swr[2][wid] = v2; }
        __syncthreads();
        if (t == 0) {
            float s0 = bs[0], s1 = bs[1], s2 = bs[2];
#pragma unroll
            for (int w = 0; w < 16; w++) { s0 += swr[0][w]; s1 += swr[1][w]; s2 += swr[2][w]; }
            float kappa = expf(s2) + kappa_prev[b];
            sm.p2.params[0] = expf(s0);
            sm.p2.params[1] = expf(s1);
            sm.p2.params[2] = kappa;
            sm.p2.params[3] = rintf(kappa);     // jnp.round = round-half-even
            if (slice == 0) {
                g_params[b][0] = sm.p2.params[0];
                g_params[b][1] = sm.p2.params[1];
                g_params[b][2] = kappa;
                g_params[b][3] = sm.p2.params[3];
            }
        }
        __syncthreads();
        int center = (int)sm.p2.params[3];

        // stage 7 ctx rows (zero-filled out of range)
        for (int c = t; c < NW * (DC / 4); c += NTHR) {
            int w  = c / (DC / 4);
            int i4 = c % (DC / 4);
            int l  = center - 3 + w;
            float4 v = make_float4(0.f, 0.f, 0.f, 0.f);
            if (l >= 0 && l < L)
                v = ((const float4*)(ctx + ((size_t)b * L + l) * DC))[i4];
            *((float4*)&sm.p2.ctx[w * DC + i4 * 4]) = v;
        }
        __syncthreads();

        // ctx-MLP: 32 i-groups x 16 j-threads (4 j each), this block's 64-j slice
        int igp = t >> 4;           // 0..31, 16 i-rows each
        int jt  = t & 15;
        int j0  = slice * 64 + jt * 4;
        int i0  = igp * 16;

        float ac[NW][4];
#pragma unroll
        for (int w = 0; w < NW; w++)
#pragma unroll
            for (int k = 0; k < 4; k++) ac[w][k] = 0.f;

#pragma unroll 4
        for (int ii = 0; ii < 16; ii++) {
            float4 wv = *((const float4*)(W1 + (size_t)(i0 + ii) * H + j0));
#pragma unroll
            for (int w = 0; w < NW; w++) {
                float c = sm.p2.ctx[w * DC + i0 + ii];
                ac[w][0] += c * wv.x;
                ac[w][1] += c * wv.y;
                ac[w][2] += c * wv.z;
                ac[w][3] += c * wv.w;
            }
        }

        // per-window: reduce 32 i-groups, tanh, dot W2-slice
        for (int w = 0; w < NW; w++) {
#pragma unroll
            for (int k = 0; k < 4; k++)
                sm.p2.red[igp * 64 + jt * 4 + k] = ac[w][k];
            __syncthreads();

            float contrib = 0.f;
            if (t < 64) {
                int j = slice * 64 + t;
                float hsum = sm.p2.qt[t];
#pragma unroll
                for (int g = 0; g < 32; g++) hsum += sm.p2.red[g * 64 + t];
                contrib = tanhf(hsum) * W2[j];
            }
#pragma unroll
            for (int o = 16; o; o >>= 1)
                contrib += __shfl_down_sync(0xffffffffu, contrib, o);
            if (t == 0 || t == 32) swr2[t >> 5] = contrib;
            __syncthreads();
            if (t == 0) g_spart[b][w][slice] = swr2[0] + swr2[1];
        }
    }

    grid_sync();

    // ================= Phase 3: posterior, normalize, outputs ==============
    if (bx < B) {
        int b = bx;
        float alpha  = g_params[b][0];
        float beta   = g_params[b][1];
        float kappa  = g_params[b][2];
        int   center = (int)g_params[b][3];

        if (t == 0) {
            float b2v = b2[0];
            float pw[NW], psum = 0.f;
#pragma unroll
            for (int w = 0; w < NW; w++) {
                int l = center - 3 + w;
                float p = 0.f;
                if (l >= 0 && l < L) {
                    float sc = b2v;
#pragma unroll
                    for (int s2 = 0; s2 < 4; s2++) sc += g_spart[b][w][s2];
                    float d = (float)l - kappa;
                    p = alpha * expf(sc - beta * d * d);
                }
                pw[w] = p;
                psum += p;
            }
            float inv = 1.f / psum;
#pragma unroll
            for (int w = 0; w < NW; w++) spw[w] = pw[w] * inv;
        }
        __syncthreads();

        // expected_ctx (ctx rows are L2-hot from phase 2)
        {
            float acc = 0.f;
#pragma unroll
            for (int w = 0; w < NW; w++) {
                int l = center - 3 + w;
                if (l >= 0 && l < L)
                    acc += spw[w] * ctx[((size_t)b * L + l) * DC + t];
            }
            out[(size_t)b * DC + t] = acc;
        }
        // sparse p_ctx writes (rest zero-filled in phase 1)
        if (t >= NTHR - NW) {
            int w = t - (NTHR - NW);
            int l = center - 3 + w;
            if (l >= 0 && l < L)
                out[(size_t)B * DC + (size_t)b * L + l] = spw[w];
        }
    }
}

// ---------------------------------------------------------------------------
extern "C" void kernel_launch(void* const* d_in, const int* in_sizes, int n_in,
                              void* d_out, int out_size)
{
    const float* query = (const float*)d_in[0];
    const float* ctx   = (const float*)d_in[1];
    const float* kprev = (const float*)d_in[2];
    const float* Wq    = (const float*)d_in[3];
    const float* bq    = (const float*)d_in[4];
    const float* Ws    = (const float*)d_in[5];
    const float* bs    = (const float*)d_in[6];
    const float* W1    = (const float*)d_in[7];
    const float* b1    = (const float*)d_in[8];
    const float* W2    = (const float*)d_in[9];
    const float* b2    = (const float*)d_in[10];

    k_all<<<NBLK, NTHR>>>(query, ctx, kprev, Wq, bq, Ws, bs, W1, b1, W2, b2,
                          (float*)d_out);
}

// round 6
// speedup vs baseline: 1.8517x; 1.1050x over previous
#include <cuda_runtime.h>
#include <math.h>

#define B    32
#define L    2048
#define DC   512
#define DQ   1024
#define H    256
#define NW   7
#define NIC  16          // i-chunks for query GEMMs (1024/64)
#define ICR  64          // rows per i-chunk
#define NBLK 128
#define NTHR 512

// scratch (no allocations allowed)
__device__ float g_pre[2][NIC][B][H];   // [0]=h-pre partials, [1]=q-part of MLP partials
__device__ float g_spart[B][NW][4];     // per-slice partial scores
__device__ unsigned g_cnt[B];           // per-batch arrival counters (monotonic)
__device__ unsigned g_bar_count = 0;
__device__ unsigned g_bar_gen   = 0;    // monotonic across graph replays

__device__ __forceinline__ void grid_sync()
{
    __syncthreads();
    if (threadIdx.x == 0) {
        __threadfence();
        unsigned gen = *(volatile unsigned*)&g_bar_gen;
        if (atomicAdd(&g_bar_count, 1) == NBLK - 1) {
            g_bar_count = 0;
            __threadfence();
            *(volatile unsigned*)&g_bar_gen = gen + 1;
        } else {
            while (*(volatile unsigned*)&g_bar_gen == gen) { }
        }
        __threadfence();
    }
    __syncthreads();
}

__global__ void __launch_bounds__(NTHR, 1)
k_all(const float* __restrict__ query,
      const float* __restrict__ ctx,
      const float* __restrict__ kappa_prev,
      const float* __restrict__ Wq,
      const float* __restrict__ bq,
      const float* __restrict__ Ws,
      const float* __restrict__ bs,
      const float* __restrict__ W1,
      const float* __restrict__ b1,
      const float* __restrict__ W2,
      const float* __restrict__ b2,
      float* __restrict__ out)
{
    int bx = blockIdx.x;        // 0..127
    int t  = threadIdx.x;       // 0..511
    int lane = t & 31;
    int wid  = t >> 5;          // 0..15

    __shared__ union {
        struct { float W[ICR * 64]; float q[B * ICR]; } p1;               // 24 KB
        struct { float ctx[NW * DC];                                      // 14 KB
                 float red[16 * NW * 64];                                 // 28 KB
                 float qt[64]; float params[4]; } p2;
    } sm;
    __shared__ float swr[3][16];
    __shared__ float swr3[NW][2];
    __shared__ float spw[NW];
    __shared__ int   s_last;

    // ================= Phase 1: query GEMM partials + p_ctx zero-fill ======
    out[(size_t)B * DC + (size_t)bx * NTHR + t] = 0.f;

    {
        int m  = bx & 1;            // 0: Wq, 1: W1 query-half
        int jc = (bx >> 1) & 3;     // j-chunk (64 cols)
        int ic = bx >> 3;           // i-chunk (64 rows)
        const float* W = m ? (W1 + (size_t)DC * H) : Wq;
        int i0 = ic * ICR;
        int j0 = jc * 64;

        for (int idx = t; idx < ICR * 16; idx += NTHR) {
            int r  = idx >> 4;
            int c4 = idx & 15;
            *((float4*)&sm.p1.W[r * 64 + c4 * 4]) =
                *((const float4*)(W + (size_t)(i0 + r) * H + j0 + c4 * 4));
        }
        {
            int b8 = t >> 4;
            int c4 = t & 15;
            *((float4*)&sm.p1.q[b8 * ICR + c4 * 4]) =
                *((const float4*)(query + (size_t)b8 * DQ + i0 + c4 * 4));
        }
        __syncthreads();

        int jt = t & 15;            // 4 j's each
        int bb = t >> 4;            // batch 0..31
        float a0 = 0.f, a1 = 0.f, a2 = 0.f, a3 = 0.f;
#pragma unroll 8
        for (int i = 0; i < ICR; i++) {
            float4 w = *((const float4*)&sm.p1.W[i * 64 + jt * 4]);
            float qv = sm.p1.q[bb * ICR + i];
            a0 += qv * w.x; a1 += qv * w.y; a2 += qv * w.z; a3 += qv * w.w;
        }
        float4 r4 = make_float4(a0, a1, a2, a3);
        *((float4*)&g_pre[m][ic][bb][j0 + jt * 4]) = r4;
    }

    grid_sync();

    // ================= Phase 2: params + ctx-MLP slice + last-block finalize
    int b     = bx >> 2;
    int slice = bx & 3;

    // h-pre reduce + tanh (t<256), qtot for this slice (t<64)
    float hval = 0.f;
    if (t < H) {
        float s = bq[t];
#pragma unroll
        for (int ic = 0; ic < NIC; ic++) s += g_pre[0][ic][b][t];
        hval = tanhf(s);
    }
    if (t < 64) {
        int j = slice * 64 + t;
        float qt = b1[j];
#pragma unroll
        for (int ic = 0; ic < NIC; ic++) qt += g_pre[1][ic][b][j];
        sm.p2.qt[t] = qt;
    }
    // stat = h @ Ws + bs
    float v0 = 0.f, v1 = 0.f, v2 = 0.f;
    if (t < H) {
        v0 = hval * Ws[t * 3 + 0];
        v1 = hval * Ws[t * 3 + 1];
        v2 = hval * Ws[t * 3 + 2];
    }
#pragma unroll
    for (int o = 16; o; o >>= 1) {
        v0 += __shfl_down_sync(0xffffffffu, v0, o);
        v1 += __shfl_down_sync(0xffffffffu, v1, o);
        v2 += __shfl_down_sync(0xffffffffu, v2, o);
    }
    if (lane == 0) { swr[0][wid] = v0; swr[1][wid] = v1; swr[2][wid] = v2; }
    __syncthreads();
    if (t == 0) {
        float s0 = bs[0], s1 = bs[1], s2 = bs[2];
#pragma unroll
        for (int w = 0; w < 16; w++) { s0 += swr[0][w]; s1 += swr[1][w]; s2 += swr[2][w]; }
        float kappa = expf(s2) + kappa_prev[b];
        sm.p2.params[0] = expf(s0);
        sm.p2.params[1] = expf(s1);
        sm.p2.params[2] = kappa;
        sm.p2.params[3] = rintf(kappa);     // jnp.round = round-half-even
    }
    __syncthreads();
    int center = (int)sm.p2.params[3];

    // stage 7 ctx rows (zero-filled out of range)
    for (int c = t; c < NW * (DC / 4); c += NTHR) {
        int w  = c / (DC / 4);
        int i4 = c % (DC / 4);
        int l  = center - 3 + w;
        float4 v = make_float4(0.f, 0.f, 0.f, 0.f);
        if (l >= 0 && l < L)
            v = ((const float4*)(ctx + ((size_t)b * L + l) * DC))[i4];
        *((float4*)&sm.p2.ctx[w * DC + i4 * 4]) = v;
    }
    __syncthreads();

    // ctx-MLP: 32 i-groups x 16 j-threads (4 j each)
    {
        int igp = t >> 4;           // 0..31, 16 i-rows each
        int jt  = t & 15;
        int j0  = slice * 64 + jt * 4;
        int i0  = igp * 16;

        float ac[NW][4];
#pragma unroll
        for (int w = 0; w < NW; w++)
#pragma unroll
            for (int k = 0; k < 4; k++) ac[w][k] = 0.f;

#pragma unroll 4
        for (int ii = 0; ii < 16; ii++) {
            float4 wv = *((const float4*)(W1 + (size_t)(i0 + ii) * H + j0));
#pragma unroll
            for (int w = 0; w < NW; w++) {
                float c = sm.p2.ctx[w * DC + i0 + ii];
                ac[w][0] += c * wv.x;
                ac[w][1] += c * wv.y;
                ac[w][2] += c * wv.z;
                ac[w][3] += c * wv.w;
            }
        }

        // fold igp pairs within warp (lanes 0-15 keep), dump once
#pragma unroll
        for (int w = 0; w < NW; w++)
#pragma unroll
            for (int k = 0; k < 4; k++) {
                float v = ac[w][k];
                v += __shfl_xor_sync(0xffffffffu, v, 16);
                if (lane < 16)
                    sm.p2.red[(wid * NW + w) * 64 + (jt & 15) * 4 + k] = v;
            }
    }
    __syncthreads();

    // single pass: 448 threads finish all 7 windows
    {
        float contrib = 0.f;
        if (t < NW * 64) {
            int w = t >> 6;
            int j = t & 63;
            float hsum = sm.p2.qt[j];
#pragma unroll
            for (int p = 0; p < 16; p++)
                hsum += sm.p2.red[(p * NW + w) * 64 + j];
            contrib = tanhf(hsum) * W2[slice * 64 + j];
        }
#pragma unroll
        for (int o = 16; o; o >>= 1)
            contrib += __shfl_down_sync(0xffffffffu, contrib, o);
        if (lane == 0 && wid < NW * 2) swr3[wid >> 1][wid & 1] = contrib;
        __syncthreads();
        if (t < NW)
            g_spart[b][t][slice] = swr3[t][0] + swr3[t][1];
    }
    __syncthreads();

    // arrival counter: last slice block of this batch finalizes
    if (t == 0) {
        __threadfence();
        unsigned old = atomicAdd(&g_cnt[b], 1u);
        s_last = ((old & 3u) == 3u);
    }
    __syncthreads();
    if (!s_last) return;

    // ================= finalize (winner block; sctx already in smem) =======
    if (t == 0) {
        __threadfence();    // acquire: other slices' g_spart stores
        float alpha = sm.p2.params[0], beta = sm.p2.params[1], kappa = sm.p2.params[2];
        float b2v = b2[0];
        float pw[NW], psum = 0.f;
#pragma unroll
        for (int w = 0; w < NW; w++) {
            int l = center - 3 + w;
            float p = 0.f;
            if (l >= 0 && l < L) {
                float sc = b2v;
#pragma unroll
                for (int s2 = 0; s2 < 4; s2++) sc += g_spart[b][w][s2];
                float d = (float)l - kappa;
                p = alpha * expf(sc - beta * d * d);
            }
            pw[w] = p;
            psum += p;
        }
        float inv = 1.f / psum;
#pragma unroll
        for (int w = 0; w < NW; w++) spw[w] = pw[w] * inv;
    }
    __syncthreads();

    // expected_ctx from smem-staged ctx rows (512 threads = DC)
    {
        float acc = 0.f;
#pragma unroll
        for (int w = 0; w < NW; w++)
            acc += spw[w] * sm.p2.ctx[w * DC + t];
        out[(size_t)b * DC + t] = acc;
    }
    // sparse p_ctx writes (rest zero-filled in phase 1, ordered by grid_sync)
    if (t < NW) {
        int l = center - 3 + t;
        if (l >= 0 && l < L)
            out[(size_t)B * DC + (size_t)b * L + l] = spw[t];
    }
}

// ---------------------------------------------------------------------------
extern "C" void kernel_launch(void* const* d_in, const int* in_sizes, int n_in,
                              void* d_out, int out_size)
{
    const float* query = (const float*)d_in[0];
    const float* ctx   = (const float*)d_in[1];
    const float* kprev = (const float*)d_in[2];
    const float* Wq    = (const float*)d_in[3];
    const float* bq    = (const float*)d_in[4];
    const float* Ws    = (const float*)d_in[5];
    const float* bs    = (const float*)d_in[6];
    const float* W1    = (const float*)d_in[7];
    const float* b1    = (const float*)d_in[8];
    const float* W2    = (const float*)d_in[9];
    const float* b2    = (const float*)d_in[10];

    k_all<<<NBLK, NTHR>>>(query, ctx, kprev, Wq, bq, Ws, bs, W1, b1, W2, b2,
                          (float*)d_out);
}